// round 15
// baseline (speedup 1.0000x reference)
#include <cuda_runtime.h>
#include <cuda_bf16.h>
#include <cuda_pipeline.h>

// CensoredLoss: outputs [B, T, V-1] f32, targets [B, T, V] f32, T=512, V=5.
// loss  = sum_{b,t} [ tgt0*log(1 - sum(out) + EPS) + sum_v tgt_{v+1}*log(out_v + EPS) ]
//         (masked rows have all-zero targets -> contribute exactly 0)
// count = #{(b,t) : sum_v targets[b,t,v] > 0}
// result = count > 0 ? -loss/count : 0
//
// Traffic/latency split (lengths ~ uniform(1,512)):
//   t in [0,256): ~75% valid -> load outputs UNCONDITIONALLY, issued BEFORE
//                 the cp.async wait (full latency overlap; ~8 MB waste).
//   t in [256,512): ~25% valid -> load outputs CONDITIONALLY on per_t > 0
//                 (skips ~75% of that half's stream).
// Net ~243 MB vs 302 MB full, with the front half overlapped.
//
// SINGLE kernel, grid = nblocks+1, 256-thread blocks, 2 rows/block;
// workers end with fire-and-forget REDs + red.release ticket; finalizer
// block spin-acquires, writes out[0], resets state for the next replay.

#define T_DIM 512
#define V_DIM 5
#define RPB   2                           // rows per worker block
#define ROW_FLOATS (T_DIM * V_DIM)        // 2560
#define EPSF  1e-8f
#define NTHREADS 256

__device__ double       g_loss;           // zero at module load; finalizer re-zeros
__device__ unsigned int g_count;
__device__ unsigned int g_ticket;

__global__ __launch_bounds__(NTHREADS, 8)
void cl_main_kernel(const float* __restrict__ outputs,
                    const float* __restrict__ targets,
                    float* __restrict__ out,
                    int nblocks)
{
    __shared__ float s_tgt[RPB * ROW_FLOATS];     // 20480 B, two rows of targets
    __shared__ float s_sum[NTHREADS / 32];
    __shared__ int   s_cnt[NTHREADS / 32];

    const int tid = threadIdx.x;

    // ---- Finalizer block (last in the grid, scheduled in the last wave) ----
    if (blockIdx.x == (unsigned)nblocks) {
        if (tid == 0) {
            unsigned int tk;
            for (;;) {
                asm volatile("ld.acquire.gpu.global.u32 %0, [%1];"
                             : "=r"(tk) : "l"(&g_ticket) : "memory");
                if (tk >= (unsigned int)nblocks) break;
                __nanosleep(128);
            }
            // Acquire synchronizes-with every worker's red.release.
            const double loss     = *((volatile double*)&g_loss);
            const unsigned int ct = *((volatile unsigned int*)&g_count);
            out[0] = (ct > 0u) ? (float)(-loss / (double)ct) : 0.0f;
            g_loss  = 0.0;
            g_count = 0u;
            *((volatile unsigned int*)&g_ticket) = 0u;
        }
        return;    // other threads exit immediately (no barrier in this block)
    }

    // ---- Worker blocks ----
    const int b0 = blockIdx.x * RPB;

    // Stage 2 rows of targets via cp.async (no register round-trip).
    {
        const float4* src = reinterpret_cast<const float4*>(
            targets + (size_t)b0 * ROW_FLOATS);
        float4* dst = reinterpret_cast<float4*>(s_tgt);
        #pragma unroll
        for (int i = tid; i < (RPB * ROW_FLOATS) / 4; i += NTHREADS)
            __pipeline_memcpy_async(&dst[i], &src[i], 16);
        __pipeline_commit();
    }

    // Unconditional prefetch of the EARLY-timestep outputs (t = tid < 256,
    // ~75% valid) so their DRAM latency overlaps the cp.async staging.
    const float4* og4 = reinterpret_cast<const float4*>(outputs);
    const float4 o00 = og4[(size_t)(b0 + 0) * T_DIM + tid];
    const float4 o10 = og4[(size_t)(b0 + 1) * T_DIM + tid];

    __pipeline_wait_prior(0);
    __syncthreads();

    float c   = 0.0f;
    int   cnt = 0;

    // k=0 half: prefetched outputs, use only if the record is valid.
    #pragma unroll
    for (int r = 0; r < RPB; r++) {
        const float4 o = (r == 0) ? o00 : o10;
        const float* q = s_tgt + r * ROW_FLOATS + tid * 5;   // gcd(5,32)=1: conflict-free
        const float t0 = q[0], t1 = q[1], t2 = q[2], t3 = q[3], t4 = q[4];
        const int nz = ((t0 + t1 + t2 + t3 + t4) > 0.0f);
        cnt += nz;
        if (nz) {
            const float censor = 1.0f - (o.x + o.y + o.z + o.w);
            c += t0 * __logf(censor + EPSF)
               + t1 * __logf(o.x + EPSF)
               + t2 * __logf(o.y + EPSF)
               + t3 * __logf(o.z + EPSF)
               + t4 * __logf(o.w + EPSF);
        }
    }

    // k=1 half (t = tid+256, ~25% valid): conditional load saves ~75% of
    // this half's outputs stream; skips are warp-coherent (prefix mask).
    #pragma unroll
    for (int r = 0; r < RPB; r++) {
        const int t = tid + 256;
        const float* q = s_tgt + r * ROW_FLOATS + t * 5;
        const float t0 = q[0], t1 = q[1], t2 = q[2], t3 = q[3], t4 = q[4];
        const int nz = ((t0 + t1 + t2 + t3 + t4) > 0.0f);
        cnt += nz;
        if (nz) {
            const float4 o = og4[(size_t)(b0 + r) * T_DIM + t];
            const float censor = 1.0f - (o.x + o.y + o.z + o.w);
            c += t0 * __logf(censor + EPSF)
               + t1 * __logf(o.x + EPSF)
               + t2 * __logf(o.y + EPSF)
               + t3 * __logf(o.z + EPSF)
               + t4 * __logf(o.w + EPSF);
        }
    }

    // Warp reduction.
    #pragma unroll
    for (int off = 16; off > 0; off >>= 1) {
        c   += __shfl_down_sync(0xffffffffu, c, off);
        cnt += __shfl_down_sync(0xffffffffu, cnt, off);
    }
    if ((tid & 31) == 0) {
        s_sum[tid >> 5] = c;
        s_cnt[tid >> 5] = cnt;
    }
    __syncthreads();

    // Final reduce across 8 warps (lanes 0..7 of warp 0), then fire-and-forget
    // REDs; the red.release ticket orders them for the finalizer's acquire.
    if (tid < NTHREADS / 32) {
        c   = s_sum[tid];
        cnt = s_cnt[tid];
        #pragma unroll
        for (int off = (NTHREADS / 64); off > 0; off >>= 1) {
            c   += __shfl_down_sync(0xffu, c, off);
            cnt += __shfl_down_sync(0xffu, cnt, off);
        }
        if (tid == 0) {
            atomicAdd(&g_loss, (double)c);           // RED.f64 (return unused)
            atomicAdd(&g_count, (unsigned int)cnt);  // RED.u32 (return unused)
            asm volatile("red.release.gpu.global.add.u32 [%0], %1;"
                         :: "l"(&g_ticket), "r"(1u) : "memory");
        }
    }
}

extern "C" void kernel_launch(void* const* d_in, const int* in_sizes, int n_in,
                              void* d_out, int out_size)
{
    const float* outputs = (const float*)d_in[0];
    const float* targets = (const float*)d_in[1];
    float* out = (float*)d_out;

    const int B       = in_sizes[1] / ROW_FLOATS;   // 16384
    const int nblocks = B / RPB;                    // 8192 worker blocks

    cl_main_kernel<<<nblocks + 1, NTHREADS>>>(outputs, targets, out, nblocks);
}